// round 12
// baseline (speedup 1.0000x reference)
#include <cuda_runtime.h>
#include <cstdint>
#include <math.h>

#define NTOK 8192
#define DIM  1024
#define NE   8
#define HIDN 2048
#define TWOH 4096

#define BM 128
#define BN 256
#define BK 32
#define NTHR 512
#define NSTAGE 4
#define LDA 36
#define LDB 264
#define STAGE_F (BM*LDA + BK*LDB)          // 4608 + 8448 = 13056 floats
#define DSMEM   (NSTAGE*STAGE_F*4)         // 208896 B (gemm1 epilogue buf 128*264*4=135168 fits)

// ---- scratch (allocation-free: __device__ globals) ----
__device__ int   g_cnt[NE];
__device__ int   g_off[NE];
__device__ int   g_list[NE*NTOK];
__device__ float g_scl[NE*NTOK];
__device__ float g_psum[NE];
__device__ float g_gbuf[(size_t)NTOK*2*HIDN];   // 128 MB

// ---- cp.async helpers ----
__device__ __forceinline__ unsigned sptr(const void* p) {
    return (unsigned)__cvta_generic_to_shared(p);
}
#define CP16(d, s)     asm volatile("cp.async.cg.shared.global [%0], [%1], 16;" ::"r"(d), "l"(s))
#define CP16Z(d, s, n) asm volatile("cp.async.cg.shared.global [%0], [%1], 16, %2;" ::"r"(d), "l"(s), "r"(n))
#define CPCOMMIT()     asm volatile("cp.async.commit_group;")
#define CPWAIT2()      asm volatile("cp.async.wait_group 2;" ::: "memory")

// ---- raw tf32 mma ----
__device__ __forceinline__ uint32_t f2tf(float x) {
    uint32_t r; asm("cvt.rna.tf32.f32 %0, %1;" : "=r"(r) : "f"(x)); return r;
}
__device__ __forceinline__ void mma8(float* d, const uint32_t* a, const uint32_t* b) {
    asm volatile("mma.sync.aligned.m16n8k8.row.col.f32.tf32.tf32.f32 "
                 "{%0,%1,%2,%3}, {%4,%5,%6,%7}, {%8,%9}, {%0,%1,%2,%3};"
                 : "+f"(d[0]), "+f"(d[1]), "+f"(d[2]), "+f"(d[3])
                 : "r"(a[0]), "r"(a[1]), "r"(a[2]), "r"(a[3]), "r"(b[0]), "r"(b[1]));
}

// =====================================================================
// init / router / finalize
// =====================================================================
__global__ void zero_small_kernel() {
    int t = threadIdx.x;
    if (t < NE) { g_cnt[t] = 0; g_psum[t] = 0.f; }
}

__global__ void zero_out_kernel(float* __restrict__ out) {
    size_t idx = (size_t)blockIdx.x * blockDim.x + threadIdx.x;
    float4 z = make_float4(0.f, 0.f, 0.f, 0.f);
    ((float4*)out)[idx] = z;
}

__global__ void router_kernel(const float* __restrict__ x,
                              const float* __restrict__ Wr,
                              const float* __restrict__ br) {
    __shared__ float sp[NE];
    int tid = threadIdx.x;
    if (tid < NE) sp[tid] = 0.f;
    __syncthreads();

    int warp = tid >> 5, lane = tid & 31;
    int t = blockIdx.x * 8 + warp;

    float acc[NE];
#pragma unroll
    for (int e = 0; e < NE; e++) acc[e] = 0.f;

    const float* xr = x + (size_t)t * DIM;
    for (int d = lane; d < DIM; d += 32) {
        float xv = xr[d];
        const float* w = Wr + d * NE;
#pragma unroll
        for (int e = 0; e < NE; e++) acc[e] += xv * w[e];
    }
#pragma unroll
    for (int o = 16; o; o >>= 1)
#pragma unroll
        for (int e = 0; e < NE; e++) acc[e] += __shfl_down_sync(0xffffffffu, acc[e], o);

    if (lane == 0) {
        float l[NE];
        float m = -1e30f;
#pragma unroll
        for (int e = 0; e < NE; e++) { l[e] = acc[e] + br[e]; m = fmaxf(m, l[e]); }
        float s = 0.f, p[NE];
#pragma unroll
        for (int e = 0; e < NE; e++) { p[e] = __expf(l[e] - m); s += p[e]; }
        float inv = 1.f / s;
#pragma unroll
        for (int e = 0; e < NE; e++) atomicAdd(&sp[e], p[e] * inv);

        int i0 = 0; float v0 = l[0];
#pragma unroll
        for (int e = 1; e < NE; e++) if (l[e] > v0) { v0 = l[e]; i0 = e; }
        int i1 = -1; float v1 = -1e30f;
#pragma unroll
        for (int e = 0; e < NE; e++) if (e != i0 && l[e] > v1) { v1 = l[e]; i1 = e; }

        float sc0 = 1.f / (1.f + __expf(v1 - v0));
        float sc1 = 1.f - sc0;

        int p0 = atomicAdd(&g_cnt[i0], 1);
        g_list[i0 * NTOK + p0] = t;  g_scl[i0 * NTOK + p0] = sc0;
        int p1 = atomicAdd(&g_cnt[i1], 1);
        g_list[i1 * NTOK + p1] = t;  g_scl[i1 * NTOK + p1] = sc1;
    }
    __syncthreads();
    if (tid < NE) atomicAdd(&g_psum[tid], sp[tid]);
}

__global__ void finalize_router(float* __restrict__ out) {
    int off = 0;
    float aux = 0.f;
    for (int e = 0; e < NE; e++) {
        g_off[e] = off;
        off += g_cnt[e];
        float f = (float)g_cnt[e] / (float)NTOK;
        float p = g_psum[e] / (float)NTOK;
        aux += f * p;
    }
    out[(size_t)NTOK * DIM] = aux * (float)NE;
}

// =====================================================================
// mainloop core: CTA 128x256 with 512 threads.
// 16 warps in 2x8 grid: warp tile 64 rows x 32 cols (4x4 m16n8k8).
// Conflict-free: A pitch 36 (bank=lane), B pitch 264 (8*(l&3)+(l>>2));
// wc*32 and nj*8 offsets preserve the pattern (0 mod 32 / uniform shift).
// =====================================================================
struct Acc { float v[4][4][4]; };

__device__ __forceinline__ void compute_stage(const float* As, const float* Bs,
                                              Acc& acc, int lane, int wr, int wc) {
    const float* aB = As + (wr * 64 + (lane >> 2)) * LDA + (lane & 3);
    const float* bB = Bs + (lane & 3) * LDB + wc * 32 + (lane >> 2);
#pragma unroll
    for (int ks = 0; ks < 4; ks++) {
        uint32_t af[4][4];
#pragma unroll
        for (int mi = 0; mi < 4; mi++) {
            const float* p = aB + mi * 16 * LDA + ks * 8;
            af[mi][0] = f2tf(p[0]);
            af[mi][1] = f2tf(p[8 * LDA]);
            af[mi][2] = f2tf(p[4]);
            af[mi][3] = f2tf(p[8 * LDA + 4]);
        }
#pragma unroll
        for (int nj = 0; nj < 4; nj++) {
            const float* q = bB + ks * 8 * LDB + nj * 8;
            uint32_t bf[2] = { f2tf(q[0]), f2tf(q[4 * LDB]) };
#pragma unroll
            for (int mi = 0; mi < 4; mi++)
                mma8(acc.v[mi][nj], af[mi], bf);
        }
    }
}

// =====================================================================
// GEMM1: D[128,256]; cols 0..127 = gate, 128..255 = up
// =====================================================================
__global__ __launch_bounds__(NTHR, 1)
void gemm1_kernel(const float* __restrict__ x,
                  const float* __restrict__ W1,
                  const float* __restrict__ b1) {
    int e = blockIdx.z;
    int cnt = g_cnt[e];
    int mbase = blockIdx.x * BM;
    if (mbase >= cnt) return;
    int base = g_off[e];
    int c0g = blockIdx.y * 128;

    extern __shared__ float dsm[];
    __shared__ int s_tok[BM];

    int tid = threadIdx.x;
    if (tid < BM) {
        int r = mbase + tid;
        s_tok[tid] = (r < cnt) ? g_list[e * NTOK + r] : -1;
    }
    __syncthreads();

    const float* W1e = W1 + (size_t)e * DIM * TWOH;

    auto fill = [&](int f) {
        int s = f % NSTAGE;
        float* As = dsm + s * STAGE_F;
        float* Bs = As + BM * LDA;
        int k0 = f * BK;
#pragma unroll
        for (int i = 0; i < 2; i++) {
            int idx = i * NTHR + tid; int row = idx >> 3; int c = idx & 7;
            int tok = s_tok[row];
            const float* src = (tok >= 0) ? x + (size_t)tok * DIM + k0 + c * 4 : x;
            CP16Z(sptr(As + row * LDA + c * 4), src, (tok >= 0) ? 16 : 0);
        }
#pragma unroll
        for (int i = 0; i < 4; i++) {
            int idx = i * NTHR + tid; int kr = idx >> 6; int c = idx & 63;
            int col = (c < 32) ? (c0g + c * 4) : (HIDN + c0g + (c - 32) * 4);
            CP16(sptr(Bs + kr * LDB + c * 4), W1e + (size_t)(k0 + kr) * TWOH + col);
        }
    };

    Acc acc;
#pragma unroll
    for (int mi = 0; mi < 4; mi++)
#pragma unroll
        for (int nj = 0; nj < 4; nj++)
#pragma unroll
            for (int q = 0; q < 4; q++) acc.v[mi][nj][q] = 0.f;

    int wid = tid >> 5, lane = tid & 31;
    int wr = wid >> 3, wc = wid & 7;

    fill(0); CPCOMMIT();
    fill(1); CPCOMMIT();
    fill(2); CPCOMMIT();

    const int T = DIM / BK;                 // 32
    for (int t = 0; t < T; t++) {
        CPWAIT2();
        __syncthreads();
        if (t + 3 < T) fill(t + 3);
        CPCOMMIT();
        const float* As = dsm + (t % NSTAGE) * STAGE_F;
        compute_stage(As, As + BM * LDA, acc, lane, wr, wc);
    }
    __syncthreads();   // all warps done with smem stages before reuse

    // stage accumulators (explicit fragment mapping), then fuse SiLU-gate
    float* buf = dsm;                        // [128][264]
    {
        int r0 = wr * 64 + (lane >> 2);
        int cb = wc * 32 + (lane & 3) * 2;
#pragma unroll
        for (int mi = 0; mi < 4; mi++)
#pragma unroll
            for (int nj = 0; nj < 4; nj++) {
                int r = r0 + mi * 16, c = cb + nj * 8;
                buf[r * LDB + c]           = acc.v[mi][nj][0];
                buf[r * LDB + c + 1]       = acc.v[mi][nj][1];
                buf[(r + 8) * LDB + c]     = acc.v[mi][nj][2];
                buf[(r + 8) * LDB + c + 1] = acc.v[mi][nj][3];
            }
    }
    __syncthreads();

    const float* b1a = b1 + (size_t)e * TWOH + c0g;
    const float* b1b = b1a + HIDN;
    int mlim = min(BM, cnt - mbase);
    for (int idx = tid; idx < 128 * 128; idx += NTHR) {
        int row = idx >> 7, c = idx & 127;
        if (row < mlim) {
            float a = buf[row * LDB + c] + b1a[c];
            float b = buf[row * LDB + 128 + c] + b1b[c];
            float gv = a * (1.f / (1.f + __expf(-a))) * b;
            g_gbuf[(size_t)(base + mbase + row) * HIDN + c0g + c] = gv;
        }
    }
}

// =====================================================================
// GEMM2: out[token] += score * (g @ W2[e] + b2[e]); direct scatter epilogue
// =====================================================================
__global__ __launch_bounds__(NTHR, 1)
void gemm2_kernel(const float* __restrict__ W2,
                  const float* __restrict__ b2,
                  float* __restrict__ out) {
    int e = blockIdx.z;
    int cnt = g_cnt[e];
    int mbase = blockIdx.x * BM;
    if (mbase >= cnt) return;
    int base = g_off[e];
    int c0 = blockIdx.y * BN;

    extern __shared__ float dsm[];
    __shared__ int   s_tok[BM];
    __shared__ float s_scl[BM];

    int tid = threadIdx.x;
    int mlim = min(BM, cnt - mbase);
    if (tid < BM) {
        int r = mbase + tid;
        if (r < cnt) { s_tok[tid] = g_list[e * NTOK + r]; s_scl[tid] = g_scl[e * NTOK + r]; }
        else         { s_tok[tid] = 0; s_scl[tid] = 0.f; }
    }
    __syncthreads();

    const float* W2e = W2 + (size_t)e * HIDN * DIM;
    const float* Ag  = g_gbuf + (size_t)(base + mbase) * HIDN;

    auto fill = [&](int f) {
        int s = f % NSTAGE;
        float* As = dsm + s * STAGE_F;
        float* Bs = As + BM * LDA;
        int k0 = f * BK;
#pragma unroll
        for (int i = 0; i < 2; i++) {
            int idx = i * NTHR + tid; int row = idx >> 3; int c = idx & 7;
            bool v = row < mlim;
            const float* src = v ? Ag + (size_t)row * HIDN + k0 + c * 4 : Ag;
            CP16Z(sptr(As + row * LDA + c * 4), src, v ? 16 : 0);
        }
#pragma unroll
        for (int i = 0; i < 4; i++) {
            int idx = i * NTHR + tid; int kr = idx >> 6; int c = idx & 63;
            CP16(sptr(Bs + kr * LDB + c * 4), W2e + (size_t)(k0 + kr) * DIM + c0 + c * 4);
        }
    };

    Acc acc;
#pragma unroll
    for (int mi = 0; mi < 4; mi++)
#pragma unroll
        for (int nj = 0; nj < 4; nj++)
#pragma unroll
            for (int q = 0; q < 4; q++) acc.v[mi][nj][q] = 0.f;

    int wid = tid >> 5, lane = tid & 31;
    int wr = wid >> 3, wc = wid & 7;

    fill(0); CPCOMMIT();
    fill(1); CPCOMMIT();
    fill(2); CPCOMMIT();

    const int T = HIDN / BK;                // 64
    for (int t = 0; t < T; t++) {
        CPWAIT2();
        __syncthreads();
        if (t + 3 < T) fill(t + 3);
        CPCOMMIT();
        const float* As = dsm + (t % NSTAGE) * STAGE_F;
        compute_stage(As, As + BM * LDA, acc, lane, wr, wc);
    }

    // direct scaled atomic scatter from accumulators
    const float* b2e = b2 + (size_t)e * DIM + c0;
    int r0 = wr * 64 + (lane >> 2);
    int cb = wc * 32 + (lane & 3) * 2;
#pragma unroll
    for (int mi = 0; mi < 4; mi++) {
#pragma unroll
        for (int h = 0; h < 2; h++) {
            int r = r0 + mi * 16 + h * 8;
            if (r < mlim) {
                int tok = s_tok[r];
                float scl = s_scl[r];
                float* outp = out + (size_t)tok * DIM + c0;
#pragma unroll
                for (int nj = 0; nj < 4; nj++) {
                    int c = cb + nj * 8;
                    atomicAdd(outp + c,     scl * (acc.v[mi][nj][h * 2]     + b2e[c]));
                    atomicAdd(outp + c + 1, scl * (acc.v[mi][nj][h * 2 + 1] + b2e[c + 1]));
                }
            }
        }
    }
}

// =====================================================================
// launch  (order chosen so ncu's fixed skip lands on gemm1)
// =====================================================================
extern "C" void kernel_launch(void* const* d_in, const int* in_sizes, int n_in,
                              void* d_out, int out_size) {
    const float* x  = (const float*)d_in[0];
    const float* Wr = (const float*)d_in[1];
    const float* br = (const float*)d_in[2];
    const float* W1 = (const float*)d_in[3];
    const float* b1 = (const float*)d_in[4];
    const float* W2 = (const float*)d_in[5];
    const float* b2 = (const float*)d_in[6];
    float* out = (float*)d_out;

    cudaFuncSetAttribute(gemm1_kernel, cudaFuncAttributeMaxDynamicSharedMemorySize, DSMEM);
    cudaFuncSetAttribute(gemm2_kernel, cudaFuncAttributeMaxDynamicSharedMemorySize, DSMEM);

    zero_small_kernel<<<1, 32>>>();
    router_kernel<<<NTOK / 8, 256>>>(x, Wr, br);
    finalize_router<<<1, 1>>>(out);                                      // writes aux at out[NTOK*DIM]
    gemm1_kernel<<<dim3(64, HIDN / 128, NE), NTHR, DSMEM>>>(x, W1, b1);  // profiled slot
    zero_out_kernel<<<8192, 256>>>(out);                                 // zeros out[0..NTOK*DIM), aux untouched
    gemm2_kernel<<<dim3(64, DIM / BN, NE), NTHR, DSMEM>>>(W2, b2, out);
}

// round 13
// speedup vs baseline: 1.0498x; 1.0498x over previous
#include <cuda_runtime.h>
#include <cstdint>
#include <math.h>

#define NTOK 8192
#define DIM  1024
#define NE   8
#define HIDN 2048
#define TWOH 4096

#define BM 128
#define BN 256
#define BK 32
#define NSTAGE 4
#define LD 36
#define LDEP 264
#define STAGE_F ((BM+BN)*LD)               // 384*36 = 13824 floats = 55296 B
#define DSMEM   (NSTAGE*STAGE_F*4)         // 221184 B (gemm1 epilogue buf 128*264*4=135168 fits)

// ---- scratch (allocation-free: __device__ globals) ----
__device__ int   g_cnt[NE];
__device__ int   g_off[NE];
__device__ int   g_list[NE*NTOK];
__device__ float g_scl[NE*NTOK];
__device__ float g_psum[NE];
__device__ float g_gbuf[(size_t)NTOK*2*HIDN];    // 128 MB (tf32-rounded)
__device__ float g_xc  [(size_t)NTOK*DIM];       //  32 MB x, tf32-rounded
__device__ float g_w1t [(size_t)NE*TWOH*DIM];    // 128 MB W1T[e][n][k], tf32-rounded
__device__ float g_w2t [(size_t)NE*DIM*HIDN];    //  64 MB W2T[e][n][k], tf32-rounded

// ---- cp.async helpers ----
__device__ __forceinline__ unsigned sptr(const void* p) {
    return (unsigned)__cvta_generic_to_shared(p);
}
#define CP16(d, s)     asm volatile("cp.async.cg.shared.global [%0], [%1], 16;" ::"r"(d), "l"(s))
#define CP16Z(d, s, n) asm volatile("cp.async.cg.shared.global [%0], [%1], 16, %2;" ::"r"(d), "l"(s), "r"(n))
#define CPCOMMIT()     asm volatile("cp.async.commit_group;")
#define CPWAIT2()      asm volatile("cp.async.wait_group 2;" ::: "memory")

// ---- tf32 helpers ----
__device__ __forceinline__ uint32_t f2tf(float x) {
    uint32_t r; asm("cvt.rna.tf32.f32 %0, %1;" : "=r"(r) : "f"(x)); return r;
}
__device__ __forceinline__ float f2tff(float x) { return __uint_as_float(f2tf(x)); }

__device__ __forceinline__ void mma8(float* d, const uint32_t* a, const uint32_t* b) {
    asm volatile("mma.sync.aligned.m16n8k8.row.col.f32.tf32.tf32.f32 "
                 "{%0,%1,%2,%3}, {%4,%5,%6,%7}, {%8,%9}, {%0,%1,%2,%3};"
                 : "+f"(d[0]), "+f"(d[1]), "+f"(d[2]), "+f"(d[3])
                 : "r"(a[0]), "r"(a[1]), "r"(a[2]), "r"(a[3]), "r"(b[0]), "r"(b[1]));
}
__device__ __forceinline__ void ldsm4(uint32_t& r0, uint32_t& r1, uint32_t& r2, uint32_t& r3,
                                      uint32_t addr) {
    asm volatile("ldmatrix.sync.aligned.m8n8.x4.shared.b16 {%0,%1,%2,%3}, [%4];"
                 : "=r"(r0), "=r"(r1), "=r"(r2), "=r"(r3) : "r"(addr));
}

// =====================================================================
// init / router / finalize
// =====================================================================
__global__ void zero_small_kernel() {
    int t = threadIdx.x;
    if (t < NE) { g_cnt[t] = 0; g_psum[t] = 0.f; }
}

__global__ void zero_out_kernel(float* __restrict__ out) {
    size_t idx = (size_t)blockIdx.x * blockDim.x + threadIdx.x;
    float4 z = make_float4(0.f, 0.f, 0.f, 0.f);
    ((float4*)out)[idx] = z;
}

__global__ void router_kernel(const float* __restrict__ x,
                              const float* __restrict__ Wr,
                              const float* __restrict__ br) {
    __shared__ float sp[NE];
    int tid = threadIdx.x;
    if (tid < NE) sp[tid] = 0.f;
    __syncthreads();

    int warp = tid >> 5, lane = tid & 31;
    int t = blockIdx.x * 8 + warp;

    float acc[NE];
#pragma unroll
    for (int e = 0; e < NE; e++) acc[e] = 0.f;

    const float* xr = x + (size_t)t * DIM;
    for (int d = lane; d < DIM; d += 32) {
        float xv = xr[d];
        const float* w = Wr + d * NE;
#pragma unroll
        for (int e = 0; e < NE; e++) acc[e] += xv * w[e];
    }
#pragma unroll
    for (int o = 16; o; o >>= 1)
#pragma unroll
        for (int e = 0; e < NE; e++) acc[e] += __shfl_down_sync(0xffffffffu, acc[e], o);

    if (lane == 0) {
        float l[NE];
        float m = -1e30f;
#pragma unroll
        for (int e = 0; e < NE; e++) { l[e] = acc[e] + br[e]; m = fmaxf(m, l[e]); }
        float s = 0.f, p[NE];
#pragma unroll
        for (int e = 0; e < NE; e++) { p[e] = __expf(l[e] - m); s += p[e]; }
        float inv = 1.f / s;
#pragma unroll
        for (int e = 0; e < NE; e++) atomicAdd(&sp[e], p[e] * inv);

        int i0 = 0; float v0 = l[0];
#pragma unroll
        for (int e = 1; e < NE; e++) if (l[e] > v0) { v0 = l[e]; i0 = e; }
        int i1 = -1; float v1 = -1e30f;
#pragma unroll
        for (int e = 0; e < NE; e++) if (e != i0 && l[e] > v1) { v1 = l[e]; i1 = e; }

        float sc0 = 1.f / (1.f + __expf(v1 - v0));
        float sc1 = 1.f - sc0;

        int p0 = atomicAdd(&g_cnt[i0], 1);
        g_list[i0 * NTOK + p0] = t;  g_scl[i0 * NTOK + p0] = sc0;
        int p1 = atomicAdd(&g_cnt[i1], 1);
        g_list[i1 * NTOK + p1] = t;  g_scl[i1 * NTOK + p1] = sc1;
    }
    __syncthreads();
    if (tid < NE) atomicAdd(&g_psum[tid], sp[tid]);
}

__global__ void finalize_router(float* __restrict__ out) {
    int off = 0;
    float aux = 0.f;
    for (int e = 0; e < NE; e++) {
        g_off[e] = off;
        off += g_cnt[e];
        float f = (float)g_cnt[e] / (float)NTOK;
        float p = g_psum[e] / (float)NTOK;
        aux += f * p;
    }
    out[(size_t)NTOK * DIM] = aux * (float)NE;
}

// =====================================================================
// prepass: tf32-round x; transpose+round W1 -> [e][n][k], W2 -> [e][n][k]
// =====================================================================
__global__ void cvt_x_kernel(const float* __restrict__ x) {
    size_t idx = (size_t)blockIdx.x * blockDim.x + threadIdx.x;   // 2M float4
    float4 v = ((const float4*)x)[idx];
    v.x = f2tff(v.x); v.y = f2tff(v.y); v.z = f2tff(v.z); v.w = f2tff(v.w);
    ((float4*)g_xc)[idx] = v;
}

__global__ void trans1_kernel(const float* __restrict__ src) {
    __shared__ float t[32][33];
    int e = blockIdx.z;
    const float* s = src + (size_t)e * DIM * TWOH;
    float* d = g_w1t + (size_t)e * TWOH * DIM;
    int cb = blockIdx.x * 32, rb = blockIdx.y * 32;
    int tx = threadIdx.x, ty = threadIdx.y;
#pragma unroll
    for (int i = ty; i < 32; i += 8) t[i][tx] = s[(size_t)(rb + i) * TWOH + cb + tx];
    __syncthreads();
#pragma unroll
    for (int i = ty; i < 32; i += 8) d[(size_t)(cb + i) * DIM + rb + tx] = f2tff(t[tx][i]);
}

__global__ void trans2_kernel(const float* __restrict__ src) {
    __shared__ float t[32][33];
    int e = blockIdx.z;
    const float* s = src + (size_t)e * HIDN * DIM;
    float* d = g_w2t + (size_t)e * DIM * HIDN;
    int cb = blockIdx.x * 32, rb = blockIdx.y * 32;
    int tx = threadIdx.x, ty = threadIdx.y;
#pragma unroll
    for (int i = ty; i < 32; i += 8) t[i][tx] = s[(size_t)(rb + i) * DIM + cb + tx];
    __syncthreads();
#pragma unroll
    for (int i = ty; i < 32; i += 8) d[(size_t)(cb + i) * HIDN + rb + tx] = f2tff(t[tx][i]);
}

// =====================================================================
// mainloop core: CTA 128x256, 8 warps, warp tile 64x64 (4x8 m16n8k8).
// A smem [m][k] pitch 36, B smem [n][k] pitch 36 (both K-major).
// Fragments via ldmatrix.x4 (b16 view of 32-bit tf32 words); no cvt
// in the mainloop (operands pre-rounded in gmem).
// =====================================================================
struct Acc { float v[4][8][4]; };

__device__ __forceinline__ void compute_stage(uint32_t sA, uint32_t sB,
                                              Acc& acc, int lane, int wr, int wc) {
    int g7 = lane & 7, g8 = lane & 8, g16 = lane & 16;
    // A: lanes 0-7: (r, k0) | 8-15: (r+8, k0) | 16-23: (r, k+4) | 24-31: (r+8, k+4)
    uint32_t aBase = sA + (uint32_t)((wr * 64 + g7 + g8) * LD) * 4u + (uint32_t)g16;
    // B: lanes 0-7: (n, k0) | 8-15: (n, k+4) | 16-23: (n+8, k0) | 24-31: (n+8, k+4)
    uint32_t bBase = sB + (uint32_t)((wc * 64 + g7 + (g16 >> 1)) * LD) * 4u + (uint32_t)(g8 << 1);
#pragma unroll
    for (int ks = 0; ks < 4; ks++) {
        uint32_t af[4][4];
#pragma unroll
        for (int mi = 0; mi < 4; mi++)
            ldsm4(af[mi][0], af[mi][1], af[mi][2], af[mi][3],
                  aBase + (uint32_t)(mi * 16 * LD * 4 + ks * 32));
        uint32_t bf[8][2];
#pragma unroll
        for (int nb = 0; nb < 4; nb++) {
            uint32_t r0, r1, r2, r3;
            ldsm4(r0, r1, r2, r3, bBase + (uint32_t)(nb * 16 * LD * 4 + ks * 32));
            bf[2 * nb][0] = r0; bf[2 * nb][1] = r1;
            bf[2 * nb + 1][0] = r2; bf[2 * nb + 1][1] = r3;
        }
#pragma unroll
        for (int nj = 0; nj < 8; nj++)
#pragma unroll
            for (int mi = 0; mi < 4; mi++)
                mma8(acc.v[mi][nj], af[mi], bf[nj]);
    }
}

// =====================================================================
// GEMM1: D[128,256]; cols 0..127 = gate, 128..255 = up
// =====================================================================
__global__ __launch_bounds__(256, 1)
void gemm1_kernel(const float* __restrict__ b1) {
    int e = blockIdx.z;
    int cnt = g_cnt[e];
    int mbase = blockIdx.x * BM;
    if (mbase >= cnt) return;
    int base = g_off[e];
    int c0g = blockIdx.y * 128;

    extern __shared__ float dsm[];
    __shared__ int s_tok[BM];

    int tid = threadIdx.x;
    if (tid < BM) {
        int r = mbase + tid;
        s_tok[tid] = (r < cnt) ? g_list[e * NTOK + r] : -1;
    }
    __syncthreads();

    const float* W1Te = g_w1t + (size_t)e * TWOH * DIM;

    auto fill = [&](int f) {
        int s = f % NSTAGE;
        float* As = dsm + s * STAGE_F;
        float* Bs = As + BM * LD;
        int k0 = f * BK;
#pragma unroll
        for (int i = 0; i < 4; i++) {
            int idx = i * 256 + tid; int row = idx >> 3; int c = idx & 7;
            int tok = s_tok[row];
            const float* src = (tok >= 0) ? g_xc + (size_t)tok * DIM + k0 + c * 4 : g_xc;
            CP16Z(sptr(As + row * LD + c * 4), src, (tok >= 0) ? 16 : 0);
        }
#pragma unroll
        for (int i = 0; i < 8; i++) {
            int idx = i * 256 + tid; int row = idx >> 3; int c = idx & 7;   // row=n 0..255
            int n = (row < 128) ? (c0g + row) : (HIDN + c0g + row - 128);
            CP16(sptr(Bs + row * LD + c * 4), W1Te + (size_t)n * DIM + k0 + c * 4);
        }
    };

    Acc acc;
#pragma unroll
    for (int mi = 0; mi < 4; mi++)
#pragma unroll
        for (int nj = 0; nj < 8; nj++)
#pragma unroll
            for (int q = 0; q < 4; q++) acc.v[mi][nj][q] = 0.f;

    int wid = tid >> 5, lane = tid & 31;
    int wr = wid >> 2, wc = wid & 3;

    fill(0); CPCOMMIT();
    fill(1); CPCOMMIT();
    fill(2); CPCOMMIT();

    const int T = DIM / BK;                 // 32
    for (int t = 0; t < T; t++) {
        CPWAIT2();
        __syncthreads();
        if (t + 3 < T) fill(t + 3);
        CPCOMMIT();
        uint32_t sA = sptr(dsm + (t % NSTAGE) * STAGE_F);
        compute_stage(sA, sA + BM * LD * 4, acc, lane, wr, wc);
    }
    __syncthreads();   // all warps done with smem stages before reuse

    // stage accumulators, then fuse SiLU-gate (write tf32-rounded g)
    float* buf = dsm;                        // [128][264]
    {
        int r0 = wr * 64 + (lane >> 2);
        int cb = wc * 64 + (lane & 3) * 2;
#pragma unroll
        for (int mi = 0; mi < 4; mi++)
#pragma unroll
            for (int nj = 0; nj < 8; nj++) {
                int r = r0 + mi * 16, c = cb + nj * 8;
                buf[r * LDEP + c]           = acc.v[mi][nj][0];
                buf[r * LDEP + c + 1]       = acc.v[mi][nj][1];
                buf[(r + 8) * LDEP + c]     = acc.v[mi][nj][2];
                buf[(r + 8) * LDEP + c + 1] = acc.v[mi][nj][3];
            }
    }
    __syncthreads();

    const float* b1a = b1 + (size_t)e * TWOH + c0g;
    const float* b1b = b1a + HIDN;
    int mlim = min(BM, cnt - mbase);
    for (int idx = tid; idx < 128 * 128; idx += 256) {
        int row = idx >> 7, c = idx & 127;
        if (row < mlim) {
            float a = buf[row * LDEP + c] + b1a[c];
            float b = buf[row * LDEP + 128 + c] + b1b[c];
            float gv = a * (1.f / (1.f + __expf(-a))) * b;
            g_gbuf[(size_t)(base + mbase + row) * HIDN + c0g + c] = f2tff(gv);
        }
    }
}

// =====================================================================
// GEMM2: out[token] += score * (g @ W2[e] + b2[e]); direct scatter epilogue
// =====================================================================
__global__ __launch_bounds__(256, 1)
void gemm2_kernel(const float* __restrict__ b2, float* __restrict__ out) {
    int e = blockIdx.z;
    int cnt = g_cnt[e];
    int mbase = blockIdx.x * BM;
    if (mbase >= cnt) return;
    int base = g_off[e];
    int c0 = blockIdx.y * BN;

    extern __shared__ float dsm[];
    __shared__ int   s_tok[BM];
    __shared__ float s_scl[BM];

    int tid = threadIdx.x;
    int mlim = min(BM, cnt - mbase);
    if (tid < BM) {
        int r = mbase + tid;
        if (r < cnt) { s_tok[tid] = g_list[e * NTOK + r]; s_scl[tid] = g_scl[e * NTOK + r]; }
        else         { s_tok[tid] = 0; s_scl[tid] = 0.f; }
    }
    __syncthreads();

    const float* W2Te = g_w2t + (size_t)e * DIM * HIDN;
    const float* Ag   = g_gbuf + (size_t)(base + mbase) * HIDN;

    auto fill = [&](int f) {
        int s = f % NSTAGE;
        float* As = dsm + s * STAGE_F;
        float* Bs = As + BM * LD;
        int k0 = f * BK;
#pragma unroll
        for (int i = 0; i < 4; i++) {
            int idx = i * 256 + tid; int row = idx >> 3; int c = idx & 7;
            bool v = row < mlim;
            const float* src = v ? Ag + (size_t)row * HIDN + k0 + c * 4 : Ag;
            CP16Z(sptr(As + row * LD + c * 4), src, v ? 16 : 0);
        }
#pragma unroll
        for (int i = 0; i < 8; i++) {
            int idx = i * 256 + tid; int row = idx >> 3; int c = idx & 7;   // row=n 0..255
            CP16(sptr(Bs + row * LD + c * 4), W2Te + (size_t)(c0 + row) * HIDN + k0 + c * 4);
        }
    };

    Acc acc;
#pragma unroll
    for (int mi = 0; mi < 4; mi++)
#pragma unroll
        for (int nj = 0; nj < 8; nj++)
#pragma unroll
            for (int q = 0; q < 4; q++) acc.v[mi][nj][q] = 0.f;

    int wid = tid >> 5, lane = tid & 31;
    int wr = wid >> 2, wc = wid & 3;

    fill(0); CPCOMMIT();
    fill(1); CPCOMMIT();
    fill(2); CPCOMMIT();

    const int T = HIDN / BK;                // 64
    for (int t = 0; t < T; t++) {
        CPWAIT2();
        __syncthreads();
        if (t + 3 < T) fill(t + 3);
        CPCOMMIT();
        uint32_t sA = sptr(dsm + (t % NSTAGE) * STAGE_F);
        compute_stage(sA, sA + BM * LD * 4, acc, lane, wr, wc);
    }

    // direct scaled atomic scatter from accumulators
    const float* b2e = b2 + (size_t)e * DIM + c0;
    int r0 = wr * 64 + (lane >> 2);
    int cb = wc * 64 + (lane & 3) * 2;
#pragma unroll
    for (int mi = 0; mi < 4; mi++) {
#pragma unroll
        for (int h = 0; h < 2; h++) {
            int r = r0 + mi * 16 + h * 8;
            if (r < mlim) {
                int tok = s_tok[r];
                float scl = s_scl[r];
                float* outp = out + (size_t)tok * DIM + c0;
#pragma unroll
                for (int nj = 0; nj < 8; nj++) {
                    int c = cb + nj * 8;
                    atomicAdd(outp + c,     scl * (acc.v[mi][nj][h * 2]     + b2e[c]));
                    atomicAdd(outp + c + 1, scl * (acc.v[mi][nj][h * 2 + 1] + b2e[c + 1]));
                }
            }
        }
    }
}

// =====================================================================
// launch  (gemm1 placed at skip-5 slot for ncu)
// =====================================================================
extern "C" void kernel_launch(void* const* d_in, const int* in_sizes, int n_in,
                              void* d_out, int out_size) {
    const float* x  = (const float*)d_in[0];
    const float* Wr = (const float*)d_in[1];
    const float* br = (const float*)d_in[2];
    const float* W1 = (const float*)d_in[3];
    const float* b1 = (const float*)d_in[4];
    const float* W2 = (const float*)d_in[5];
    const float* b2 = (const float*)d_in[6];
    float* out = (float*)d_out;

    cudaFuncSetAttribute(gemm1_kernel, cudaFuncAttributeMaxDynamicSharedMemorySize, DSMEM);
    cudaFuncSetAttribute(gemm2_kernel, cudaFuncAttributeMaxDynamicSharedMemorySize, DSMEM);

    zero_small_kernel<<<1, 32>>>();                                        // 0
    router_kernel<<<NTOK / 8, 256>>>(x, Wr, br);                           // 1
    finalize_router<<<1, 1>>>(out);                                        // 2
    cvt_x_kernel<<<8192, 256>>>(x);                                        // 3
    trans1_kernel<<<dim3(TWOH / 32, DIM / 32, NE), dim3(32, 8)>>>(W1);     // 4
    gemm1_kernel<<<dim3(64, HIDN / 128, NE), 256, DSMEM>>>(b1);            // 5 (profiled)
    zero_out_kernel<<<8192, 256>>>(out);                                   // 6
    trans2_kernel<<<dim3(DIM / 32, HIDN / 32, NE), dim3(32, 8)>>>(W2);     // 7
    gemm2_kernel<<<dim3(64, DIM / BN, NE), 256, DSMEM>>>(b2, out);         // 8
}

// round 14
// speedup vs baseline: 1.0958x; 1.0438x over previous
#include <cuda_runtime.h>
#include <cstdint>
#include <math.h>

#define NTOK 8192
#define DIM  1024
#define NE   8
#define HIDN 2048
#define TWOH 4096

#define BM 128
#define BN 256
#define BK 32
#define NSTAGE 4
#define LDA 36
#define LDB 264
#define STAGE_F (BM*LDA + BK*LDB)          // 13056 floats
#define DSMEM   (NSTAGE*STAGE_F*4)         // 208896 B
#define MAXW 136                            // max occupied m-tiles: 16384/128 + 8 partials

// ---- scratch (allocation-free: __device__ globals) ----
__device__ int   g_cnt[NE];
__device__ int   g_off[NE];
__device__ int   g_list[NE*NTOK];
__device__ float g_scl[NE*NTOK];
__device__ float g_psum[NE];
__device__ int2  g_work[MAXW];
__device__ int   g_nwork;
__device__ float g_gbuf[(size_t)NTOK*2*HIDN];   // 128 MB

// ---- cp.async helpers ----
__device__ __forceinline__ unsigned sptr(const void* p) {
    return (unsigned)__cvta_generic_to_shared(p);
}
#define CP16(d, s)     asm volatile("cp.async.cg.shared.global [%0], [%1], 16;" ::"r"(d), "l"(s))
#define CP16Z(d, s, n) asm volatile("cp.async.cg.shared.global [%0], [%1], 16, %2;" ::"r"(d), "l"(s), "r"(n))
#define CPCOMMIT()     asm volatile("cp.async.commit_group;")
#define CPWAIT2()      asm volatile("cp.async.wait_group 2;" ::: "memory")

// ---- raw tf32 mma ----
__device__ __forceinline__ uint32_t f2tf(float x) {
    uint32_t r; asm("cvt.rna.tf32.f32 %0, %1;" : "=r"(r) : "f"(x)); return r;
}
__device__ __forceinline__ void mma8(float* d, const uint32_t* a, const uint32_t* b) {
    asm volatile("mma.sync.aligned.m16n8k8.row.col.f32.tf32.tf32.f32 "
                 "{%0,%1,%2,%3}, {%4,%5,%6,%7}, {%8,%9}, {%0,%1,%2,%3};"
                 : "+f"(d[0]), "+f"(d[1]), "+f"(d[2]), "+f"(d[3])
                 : "r"(a[0]), "r"(a[1]), "r"(a[2]), "r"(a[3]), "r"(b[0]), "r"(b[1]));
}

// =====================================================================
// init / router / finalize
// =====================================================================
__global__ void zero_small_kernel() {
    int t = threadIdx.x;
    if (t < NE) { g_cnt[t] = 0; g_psum[t] = 0.f; }
}

__global__ void zero_out_kernel(float* __restrict__ out, int ofs) {
    size_t idx = (size_t)(blockIdx.x + ofs) * blockDim.x + threadIdx.x;
    float4 z = make_float4(0.f, 0.f, 0.f, 0.f);
    ((float4*)out)[idx] = z;
}

__global__ void router_kernel(const float* __restrict__ x,
                              const float* __restrict__ Wr,
                              const float* __restrict__ br) {
    __shared__ float sp[NE];
    int tid = threadIdx.x;
    if (tid < NE) sp[tid] = 0.f;
    __syncthreads();

    int warp = tid >> 5, lane = tid & 31;
    int t = blockIdx.x * 8 + warp;

    float acc[NE];
#pragma unroll
    for (int e = 0; e < NE; e++) acc[e] = 0.f;

    const float* xr = x + (size_t)t * DIM;
    for (int d = lane; d < DIM; d += 32) {
        float xv = xr[d];
        const float* w = Wr + d * NE;
#pragma unroll
        for (int e = 0; e < NE; e++) acc[e] += xv * w[e];
    }
#pragma unroll
    for (int o = 16; o; o >>= 1)
#pragma unroll
        for (int e = 0; e < NE; e++) acc[e] += __shfl_down_sync(0xffffffffu, acc[e], o);

    if (lane == 0) {
        float l[NE];
        float m = -1e30f;
#pragma unroll
        for (int e = 0; e < NE; e++) { l[e] = acc[e] + br[e]; m = fmaxf(m, l[e]); }
        float s = 0.f, p[NE];
#pragma unroll
        for (int e = 0; e < NE; e++) { p[e] = __expf(l[e] - m); s += p[e]; }
        float inv = 1.f / s;
#pragma unroll
        for (int e = 0; e < NE; e++) atomicAdd(&sp[e], p[e] * inv);

        int i0 = 0; float v0 = l[0];
#pragma unroll
        for (int e = 1; e < NE; e++) if (l[e] > v0) { v0 = l[e]; i0 = e; }
        int i1 = -1; float v1 = -1e30f;
#pragma unroll
        for (int e = 0; e < NE; e++) if (e != i0 && l[e] > v1) { v1 = l[e]; i1 = e; }

        float sc0 = 1.f / (1.f + __expf(v1 - v0));
        float sc1 = 1.f - sc0;

        int p0 = atomicAdd(&g_cnt[i0], 1);
        g_list[i0 * NTOK + p0] = t;  g_scl[i0 * NTOK + p0] = sc0;
        int p1 = atomicAdd(&g_cnt[i1], 1);
        g_list[i1 * NTOK + p1] = t;  g_scl[i1 * NTOK + p1] = sc1;
    }
    __syncthreads();
    if (tid < NE) atomicAdd(&g_psum[tid], sp[tid]);
}

// prefix offsets + aux loss + dense m-tile work list
__global__ void finalize_router(float* __restrict__ out) {
    int off = 0;
    float aux = 0.f;
    int w = 0;
    for (int e = 0; e < NE; e++) {
        g_off[e] = off;
        int c = g_cnt[e];
        off += c;
        float f = (float)c / (float)NTOK;
        float p = g_psum[e] / (float)NTOK;
        aux += f * p;
        for (int mb = 0; mb < c; mb += BM) {
            g_work[w].x = e; g_work[w].y = mb; w++;
        }
    }
    g_nwork = w;
    out[(size_t)NTOK * DIM] = aux * (float)NE;
}

// =====================================================================
// mainloop core: CTA 128x256, warp 64x64 (4x8 m16n8k8), BK=32.
// Conflict-free: A pitch 36 (bank=lane), B pitch 264 (8*(l&3)+(l>>2)).
// Fragment loads double-buffered at ks granularity.
// =====================================================================
struct Acc { float v[4][8][4]; };

__device__ __forceinline__ void ldFragA(const float* aB, int ks, uint32_t af[4][4]) {
#pragma unroll
    for (int mi = 0; mi < 4; mi++) {
        const float* p = aB + mi * 16 * LDA + ks * 8;
        af[mi][0] = f2tf(p[0]);
        af[mi][1] = f2tf(p[8 * LDA]);
        af[mi][2] = f2tf(p[4]);
        af[mi][3] = f2tf(p[8 * LDA + 4]);
    }
}
__device__ __forceinline__ void ldFragB(const float* bB, int ks, uint32_t bf[8][2]) {
#pragma unroll
    for (int nj = 0; nj < 8; nj++) {
        const float* q = bB + ks * 8 * LDB + nj * 8;
        bf[nj][0] = f2tf(q[0]);
        bf[nj][1] = f2tf(q[4 * LDB]);
    }
}

__device__ __forceinline__ void compute_stage(const float* As, const float* Bs,
                                              Acc& acc, int lane, int wr, int wc) {
    const float* aB = As + (wr * 64 + (lane >> 2)) * LDA + (lane & 3);
    const float* bB = Bs + (lane & 3) * LDB + wc * 64 + (lane >> 2);
    uint32_t afb[2][4][4], bfb[2][8][2];
    ldFragA(aB, 0, afb[0]);
    ldFragB(bB, 0, bfb[0]);
#pragma unroll
    for (int ks = 0; ks < 4; ks++) {
        int cur = ks & 1, nxt = cur ^ 1;
        if (ks < 3) {
            ldFragA(aB, ks + 1, afb[nxt]);
            ldFragB(bB, ks + 1, bfb[nxt]);
        }
#pragma unroll
        for (int nj = 0; nj < 8; nj++)
#pragma unroll
            for (int mi = 0; mi < 4; mi++)
                mma8(acc.v[mi][nj], afb[cur][mi], bfb[cur][nj]);
    }
}

// =====================================================================
// GEMM1: D[128,256]; cols 0..127 = gate, 128..255 = up
// grid (MAXW, 16): work-list compacted
// =====================================================================
__global__ __launch_bounds__(256, 1)
void gemm1_kernel(const float* __restrict__ x,
                  const float* __restrict__ W1,
                  const float* __restrict__ b1) {
    if (blockIdx.x >= g_nwork) return;
    int2 wk = g_work[blockIdx.x];
    int e = wk.x, mbase = wk.y;
    int cnt = g_cnt[e];
    int base = g_off[e];
    int c0g = blockIdx.y * 128;

    extern __shared__ float dsm[];
    __shared__ int s_tok[BM];

    int tid = threadIdx.x;
    if (tid < BM) {
        int r = mbase + tid;
        s_tok[tid] = (r < cnt) ? g_list[e * NTOK + r] : -1;
    }
    __syncthreads();

    const float* W1e = W1 + (size_t)e * DIM * TWOH;

    auto fill = [&](int f) {
        int s = f % NSTAGE;
        float* As = dsm + s * STAGE_F;
        float* Bs = As + BM * LDA;
        int k0 = f * BK;
#pragma unroll
        for (int i = 0; i < 4; i++) {
            int idx = i * 256 + tid; int row = idx >> 3; int c = idx & 7;
            int tok = s_tok[row];
            const float* src = (tok >= 0) ? x + (size_t)tok * DIM + k0 + c * 4 : x;
            CP16Z(sptr(As + row * LDA + c * 4), src, (tok >= 0) ? 16 : 0);
        }
#pragma unroll
        for (int i = 0; i < 8; i++) {
            int idx = i * 256 + tid; int kr = idx >> 6; int c = idx & 63;
            int col = (c < 32) ? (c0g + c * 4) : (HIDN + c0g + (c - 32) * 4);
            CP16(sptr(Bs + kr * LDB + c * 4), W1e + (size_t)(k0 + kr) * TWOH + col);
        }
    };

    Acc acc;
#pragma unroll
    for (int mi = 0; mi < 4; mi++)
#pragma unroll
        for (int nj = 0; nj < 8; nj++)
#pragma unroll
            for (int q = 0; q < 4; q++) acc.v[mi][nj][q] = 0.f;

    int wid = tid >> 5, lane = tid & 31;
    int wr = wid >> 2, wc = wid & 3;

    fill(0); CPCOMMIT();
    fill(1); CPCOMMIT();
    fill(2); CPCOMMIT();

    const int T = DIM / BK;                 // 32
    for (int t = 0; t < T; t++) {
        CPWAIT2();
        __syncthreads();
        if (t + 3 < T) fill(t + 3);
        CPCOMMIT();
        const float* As = dsm + (t % NSTAGE) * STAGE_F;
        compute_stage(As, As + BM * LDA, acc, lane, wr, wc);
    }
    __syncthreads();   // all warps done with smem stages before reuse

    // stage accumulators, then fuse SiLU-gate
    float* buf = dsm;                        // [128][264]
    {
        int r0 = wr * 64 + (lane >> 2);
        int cb = wc * 64 + (lane & 3) * 2;
#pragma unroll
        for (int mi = 0; mi < 4; mi++)
#pragma unroll
            for (int nj = 0; nj < 8; nj++) {
                int r = r0 + mi * 16, c = cb + nj * 8;
                buf[r * LDB + c]           = acc.v[mi][nj][0];
                buf[r * LDB + c + 1]       = acc.v[mi][nj][1];
                buf[(r + 8) * LDB + c]     = acc.v[mi][nj][2];
                buf[(r + 8) * LDB + c + 1] = acc.v[mi][nj][3];
            }
    }
    __syncthreads();

    const float* b1a = b1 + (size_t)e * TWOH + c0g;
    const float* b1b = b1a + HIDN;
    int mlim = min(BM, cnt - mbase);
    for (int idx = tid; idx < 128 * 128; idx += 256) {
        int row = idx >> 7, c = idx & 127;
        if (row < mlim) {
            float a = buf[row * LDB + c] + b1a[c];
            float b = buf[row * LDB + 128 + c] + b1b[c];
            float gv = a * (1.f / (1.f + __expf(-a))) * b;
            g_gbuf[(size_t)(base + mbase + row) * HIDN + c0g + c] = gv;
        }
    }
}

// =====================================================================
// GEMM2: out[token] += score * (g @ W2[e] + b2[e]); direct scatter epilogue
// grid (MAXW, 4): work-list compacted
// =====================================================================
__global__ __launch_bounds__(256, 1)
void gemm2_kernel(const float* __restrict__ W2,
                  const float* __restrict__ b2,
                  float* __restrict__ out) {
    if (blockIdx.x >= g_nwork) return;
    int2 wk = g_work[blockIdx.x];
    int e = wk.x, mbase = wk.y;
    int cnt = g_cnt[e];
    int base = g_off[e];
    int c0 = blockIdx.y * BN;

    extern __shared__ float dsm[];
    __shared__ int   s_tok[BM];
    __shared__ float s_scl[BM];

    int tid = threadIdx.x;
    int mlim = min(BM, cnt - mbase);
    if (tid < BM) {
        int r = mbase + tid;
        if (r < cnt) { s_tok[tid] = g_list[e * NTOK + r]; s_scl[tid] = g_scl[e * NTOK + r]; }
        else         { s_tok[tid] = 0; s_scl[tid] = 0.f; }
    }
    __syncthreads();

    const float* W2e = W2 + (size_t)e * HIDN * DIM;
    const float* Ag  = g_gbuf + (size_t)(base + mbase) * HIDN;

    auto fill = [&](int f) {
        int s = f % NSTAGE;
        float* As = dsm + s * STAGE_F;
        float* Bs = As + BM * LDA;
        int k0 = f * BK;
#pragma unroll
        for (int i = 0; i < 4; i++) {
            int idx = i * 256 + tid; int row = idx >> 3; int c = idx & 7;
            bool v = row < mlim;
            const float* src = v ? Ag + (size_t)row * HIDN + k0 + c * 4 : Ag;
            CP16Z(sptr(As + row * LDA + c * 4), src, v ? 16 : 0);
        }
#pragma unroll
        for (int i = 0; i < 8; i++) {
            int idx = i * 256 + tid; int kr = idx >> 6; int c = idx & 63;
            CP16(sptr(Bs + kr * LDB + c * 4), W2e + (size_t)(k0 + kr) * DIM + c0 + c * 4);
        }
    };

    Acc acc;
#pragma unroll
    for (int mi = 0; mi < 4; mi++)
#pragma unroll
        for (int nj = 0; nj < 8; nj++)
#pragma unroll
            for (int q = 0; q < 4; q++) acc.v[mi][nj][q] = 0.f;

    int wid = tid >> 5, lane = tid & 31;
    int wr = wid >> 2, wc = wid & 3;

    fill(0); CPCOMMIT();
    fill(1); CPCOMMIT();
    fill(2); CPCOMMIT();

    const int T = HIDN / BK;                // 64
    for (int t = 0; t < T; t++) {
        CPWAIT2();
        __syncthreads();
        if (t + 3 < T) fill(t + 3);
        CPCOMMIT();
        const float* As = dsm + (t % NSTAGE) * STAGE_F;
        compute_stage(As, As + BM * LDA, acc, lane, wr, wc);
    }

    // direct scaled atomic scatter from accumulators
    const float* b2e = b2 + (size_t)e * DIM + c0;
    int r0 = wr * 64 + (lane >> 2);
    int cb = wc * 64 + (lane & 3) * 2;
#pragma unroll
    for (int mi = 0; mi < 4; mi++) {
#pragma unroll
        for (int h = 0; h < 2; h++) {
            int r = r0 + mi * 16 + h * 8;
            if (r < mlim) {
                int tok = s_tok[r];
                float scl = s_scl[r];
                float* outp = out + (size_t)tok * DIM + c0;
#pragma unroll
                for (int nj = 0; nj < 8; nj++) {
                    int c = cb + nj * 8;
                    atomicAdd(outp + c,     scl * (acc.v[mi][nj][h * 2]     + b2e[c]));
                    atomicAdd(outp + c + 1, scl * (acc.v[mi][nj][h * 2 + 1] + b2e[c + 1]));
                }
            }
        }
    }
}

// =====================================================================
// launch  (gemm1 at ncu skip-5 slot)
// =====================================================================
extern "C" void kernel_launch(void* const* d_in, const int* in_sizes, int n_in,
                              void* d_out, int out_size) {
    const float* x  = (const float*)d_in[0];
    const float* Wr = (const float*)d_in[1];
    const float* br = (const float*)d_in[2];
    const float* W1 = (const float*)d_in[3];
    const float* b1 = (const float*)d_in[4];
    const float* W2 = (const float*)d_in[5];
    const float* b2 = (const float*)d_in[6];
    float* out = (float*)d_out;

    cudaFuncSetAttribute(gemm1_kernel, cudaFuncAttributeMaxDynamicSharedMemorySize, DSMEM);
    cudaFuncSetAttribute(gemm2_kernel, cudaFuncAttributeMaxDynamicSharedMemorySize, DSMEM);

    zero_small_kernel<<<1, 32>>>();                                      // 0
    router_kernel<<<NTOK / 8, 256>>>(x, Wr, br);                         // 1
    finalize_router<<<1, 1>>>(out);                                      // 2
    zero_out_kernel<<<4096, 256>>>(out, 0);                              // 3
    zero_out_kernel<<<4096, 256>>>(out, 4096);                           // 4
    gemm1_kernel<<<dim3(MAXW, HIDN / 128), 256, DSMEM>>>(x, W1, b1);     // 5 (profiled)
    gemm2_kernel<<<dim3(MAXW, DIM / BN), 256, DSMEM>>>(W2, b2, out);     // 6
}